// round 5
// baseline (speedup 1.0000x reference)
#include <cuda_runtime.h>
#include <cstdint>

// YOLOv1 loss: [B,7,7,30] x2 f32 -> scalar. HBM-bound (~193 MB read).
// R5: split scheme. Only the 15 cell-gathered floats (t[0..4], p[0..9]) are
// staged in element-major smem (7.7 KB/block, conflict-free phase-B reads).
// Class elements (e>=10) are diffed+squared straight from the coalesced LDG
// stream and deferred in registers, gated later by conf from smem.
// 6 blocks/SM x 4 warps = 2x the warps of R4; latency hidden by SMT.

#define TPB    128
#define CPB    128
#define DIM    30
#define NV4T   ((CPB * DIM) / 4)   // 960 float4 per tensor per tile
#define EPSF   1e-6f
#define MAX_BLOCKS 16384

__device__ float g_part[MAX_BLOCKS];
__device__ unsigned int g_count = 0;

__device__ __forceinline__ float sq(float x) { return x * x; }

__device__ __forceinline__ float iou5(float tx, float ty, float tw, float th,
                                      float px, float py, float pw, float ph) {
    float ax1 = tx - 0.5f * tw, ax2 = tx + 0.5f * tw;
    float ay1 = ty - 0.5f * th, ay2 = ty + 0.5f * th;
    float bx1 = px - 0.5f * pw, bx2 = px + 0.5f * pw;
    float by1 = py - 0.5f * ph, by2 = py + 0.5f * ph;
    float iw = fmaxf(fminf(ax2, bx2) - fmaxf(ax1, bx1), 0.0f);
    float ih = fmaxf(fminf(ay2, by2) - fmaxf(ay1, by1), 0.0f);
    float inter = iw * ih;
    float a1 = fabsf((ax2 - ax1) * (ay2 - ay1));
    float a2 = fabsf((bx2 - bx1) * (by2 - by1));
    return inter / (a1 + a2 - inter + EPSF);
}

__global__ void __launch_bounds__(TPB, 6)
yolo_loss_kernel(const float* __restrict__ yt_g,
                 const float* __restrict__ yp_g,
                 long long n_cells,
                 long long n_tiles,
                 float* __restrict__ out,
                 double inv_batch) {
    // Element-major staging: rows 0..4 = t[0..4], rows 5..14 = p[0..9].
    __shared__ float sb[15][CPB];          // 7680 B
    __shared__ float wsum[TPB / 32];
    __shared__ int   s_last;

    const int tid = threadIdx.x;

    // Per-thread element map for j_i = i*TPB + tid, f = 4*j:
    // f_i = 4*tid + 512*i  ->  e_i = e_base + 2i (one wrap), c_i = c_base + 17i (+wrap)
    const int f0     = 4 * tid;
    const int c_base = f0 / DIM;
    const int e_base = f0 - DIM * c_base;

    float acc = 0.0f;

    for (long long t = blockIdx.x; t < n_tiles; t += gridDim.x) {
        long long base = t * CPB;
        bool fullTile = (base + CPB <= n_cells);

        if (fullTile) {
            const float4* yt4 = (const float4*)(yt_g + base * DIM);
            const float4* yp4 = (const float4*)(yp_g + base * DIM);

            float sA[8], sB[8];
#pragma unroll
            for (int i = 0; i < 8; i++) { sA[i] = 0.0f; sB[i] = 0.0f; }

            // ---- Phase A: two batches of 4 float4-pairs (front-batched LDGs) ----
#pragma unroll
            for (int half = 0; half < 2; half++) {
                float4 tq[4], pq[4];
#pragma unroll
                for (int u = 0; u < 4; u++) {
                    int i = half * 4 + u;
                    int j = i * TPB + tid;
                    if (j < NV4T) { tq[u] = yt4[j]; pq[u] = yp4[j]; }
                }
#pragma unroll
                for (int u = 0; u < 4; u++) {
                    int i = half * 4 + u;
                    int j = i * TPB + tid;
                    if (j < NV4T) {
                        int e = e_base + 2 * i;
                        int c = c_base + 17 * i;
                        if (e >= DIM) { e -= DIM; c += 1; }
                        int cFirst = c;
                        float tv[4] = {tq[u].x, tq[u].y, tq[u].z, tq[u].w};
                        float pv[4] = {pq[u].x, pq[u].y, pq[u].z, pq[u].w};
#pragma unroll
                        for (int q = 0; q < 4; q++) {
                            if (e < 10) {
                                if (e < 5) sb[e][c] = tv[q];
                                sb[5 + e][c] = pv[q];
                            } else {
                                float d = sq(tv[q] - pv[q]);
                                if (c == cFirst) sA[i] += d; else sB[i] += d;
                            }
                            e++;
                            if (e == DIM) { e = 0; c++; }
                        }
                    }
                }
            }
            __syncthreads();

            // ---- Phase B: thread = cell (conflict-free element-major reads) ----
            {
                float t0 = sb[0][tid], t1 = sb[1][tid], t2 = sb[2][tid];
                float t3 = sb[3][tid], t4v = sb[4][tid];
                float p0 = sb[5][tid],  p1 = sb[6][tid],  p2 = sb[7][tid];
                float p3 = sb[8][tid],  p4 = sb[9][tid],  p5 = sb[10][tid];
                float p6 = sb[11][tid], p7 = sb[12][tid], p8 = sb[13][tid];
                float p9 = sb[14][tid];

                float obj = (t4v == 1.0f) ? 1.0f : 0.0f;

                float iou1 = iou5(t0, t1, t2, t3, p0, p1, p2, p3);
                float iou2 = iou5(t0, t1, t2, t3, p5, p6, p7, p8);
                bool best1 = iou1 > iou2;

                float bx = best1 ? p0 : p5, by = best1 ? p1 : p6;
                float bw = best1 ? p2 : p7, bh = best1 ? p3 : p8;
                float ch = best1 ? p4 : p9, oh = best1 ? p9 : p4;

                float xy = sq(t0 - bx) + sq(t1 - by);
                float wh = sq(sqrtf(t2) - sqrtf(fabsf(bw + EPSF)))
                         + sq(sqrtf(t3) - sqrtf(fabsf(bh + EPSF)));
                float obj_conf = sq(t4v - ch);
                float noio = 0.5f * oh * oh;
                float noc  = 0.5f * (sq(t4v - p4) + sq(t4v - p9));

                acc += obj * (5.0f * (xy + wh) + obj_conf + noio)
                     + (1.0f - obj) * noc;

                // Gate deferred class sums by conf of their cells.
#pragma unroll
                for (int i = 0; i < 8; i++) {
                    int j = i * TPB + tid;
                    if (j < NV4T) {
                        int e = e_base + 2 * i;
                        int c = c_base + 17 * i;
                        if (e >= DIM) c += 1;
                        float cfA = sb[4][c];
                        if (cfA == 1.0f) acc += sA[i];
                        int cB = c + 1; if (cB > CPB - 1) cB = CPB - 1;
                        float cfB = sb[4][cB];
                        if (cfB == 1.0f) acc += sB[i];
                    }
                }
            }
            __syncthreads();   // sb reads done before next tile overwrites
        } else {
            // Tail tile (not hit at bench size): direct per-cell gmem path.
            int cells = (int)(n_cells - base);
            if (tid < cells) {
                const float* tt = yt_g + (base + tid) * DIM;
                const float* pp = yp_g + (base + tid) * DIM;
                float t0 = tt[0], t1 = tt[1], t2 = tt[2], t3 = tt[3], t4v = tt[4];
                float p0 = pp[0], p1 = pp[1], p2 = pp[2], p3 = pp[3], p4 = pp[4];
                float p5 = pp[5], p6 = pp[6], p7 = pp[7], p8 = pp[8], p9 = pp[9];

                float obj = (t4v == 1.0f) ? 1.0f : 0.0f;
                float iou1 = iou5(t0, t1, t2, t3, p0, p1, p2, p3);
                float iou2 = iou5(t0, t1, t2, t3, p5, p6, p7, p8);
                bool best1 = iou1 > iou2;
                float bx = best1 ? p0 : p5, by = best1 ? p1 : p6;
                float bw = best1 ? p2 : p7, bh = best1 ? p3 : p8;
                float ch = best1 ? p4 : p9, oh = best1 ? p9 : p4;
                float xy = sq(t0 - bx) + sq(t1 - by);
                float wh = sq(sqrtf(t2) - sqrtf(fabsf(bw + EPSF)))
                         + sq(sqrtf(t3) - sqrtf(fabsf(bh + EPSF)));
                float obj_conf = sq(t4v - ch);
                float noio = 0.5f * oh * oh;
                float noc  = 0.5f * (sq(t4v - p4) + sq(t4v - p9));
                float cls = 0.0f;
#pragma unroll
                for (int k = 0; k < 20; k++) cls += sq(tt[10 + k] - pp[10 + k]);
                acc += obj * (5.0f * (xy + wh) + obj_conf + noio + cls)
                     + (1.0f - obj) * noc;
            }
        }
    }

    // Block reduction (once).
#pragma unroll
    for (int o = 16; o > 0; o >>= 1)
        acc += __shfl_xor_sync(0xFFFFFFFFu, acc, o);

    int lane = tid & 31;
    int warp = tid >> 5;
    if (lane == 0) wsum[warp] = acc;
    __syncthreads();

    if (tid == 0) {
        float s = 0.0f;
#pragma unroll
        for (int i = 0; i < TPB / 32; i++) s += wsum[i];
        g_part[blockIdx.x] = s;
        __threadfence();
        unsigned int prev = atomicAdd(&g_count, 1u);
        s_last = (prev == gridDim.x - 1) ? 1 : 0;
    }
    __syncthreads();

    if (s_last) {
        int nb = gridDim.x;
        const volatile float* vp = g_part;
        double s = 0.0;
        for (int i = tid; i < nb; i += TPB)
            s += (double)vp[i];
#pragma unroll
        for (int o = 16; o > 0; o >>= 1)
            s += __shfl_xor_sync(0xFFFFFFFFu, s, o);

        __shared__ double dsum[TPB / 32];
        if (lane == 0) dsum[warp] = s;
        __syncthreads();

        if (tid == 0) {
            double tot = 0.0;
#pragma unroll
            for (int i = 0; i < TPB / 32; i++) tot += dsum[i];
            out[0] = (float)(tot * inv_batch);
            g_count = 0;   // reset for next graph replay
        }
    }
}

extern "C" void kernel_launch(void* const* d_in, const int* in_sizes, int n_in,
                              void* d_out, int out_size) {
    const float* yt = (const float*)d_in[0];   // y_trues
    const float* yp = (const float*)d_in[1];   // y_preds
    long long n_cells = (long long)in_sizes[0] / DIM;     // batch * 49
    long long batch   = n_cells / 49;
    long long n_tiles = (n_cells + CPB - 1) / CPB;

    int blocks = (n_tiles < (long long)MAX_BLOCKS) ? (int)n_tiles : MAX_BLOCKS;

    yolo_loss_kernel<<<blocks, TPB>>>(yt, yp, n_cells, n_tiles,
                                      (float*)d_out, 1.0 / (double)batch);
}

// round 6
// speedup vs baseline: 1.4452x; 1.4452x over previous
#include <cuda_runtime.h>
#include <cstdint>

// YOLOv1 loss: [B,7,7,30] x2 f32 -> scalar. HBM-bound (~193 MB read).
// R6: warp-autonomous double-buffered pipelines. Each warp owns a private
// 16-cell tile (7.68 KB incl. both stages), issues cp.async for its own
// tiles, waits with per-thread cp.async groups -> NO block barriers in the
// main loop. 4 warps/block, 30.7 KB static smem -> 7 blocks/SM = 28 warps
// (vs 12 in R4). Lanes 0-15 compute thread-per-cell; all lanes load.

#define TPB    128
#define NWARP  (TPB / 32)
#define DIM    30
#define CW     16                 // cells per warp-tile
#define WFL    (CW * DIM)         // 480 floats per tensor per warp-tile
#define NV4W   (WFL / 4)          // 120 float4
#define EPSF   1e-6f
#define MAX_BLOCKS 2048

__device__ float g_part[MAX_BLOCKS];
__device__ unsigned int g_count = 0;

__device__ __forceinline__ float sq(float x) { return x * x; }

__device__ __forceinline__ void cp16(uint32_t smem_dst, const void* gsrc) {
    asm volatile("cp.async.cg.shared.global [%0], [%1], 16;\n"
                 :: "r"(smem_dst), "l"(gsrc));
}
__device__ __forceinline__ void cp4(uint32_t smem_dst, const void* gsrc) {
    asm volatile("cp.async.ca.shared.global [%0], [%1], 4;\n"
                 :: "r"(smem_dst), "l"(gsrc));
}

__device__ __forceinline__ float iou5(float tx, float ty, float tw, float th,
                                      float px, float py, float pw, float ph) {
    float ax1 = tx - 0.5f * tw, ax2 = tx + 0.5f * tw;
    float ay1 = ty - 0.5f * th, ay2 = ty + 0.5f * th;
    float bx1 = px - 0.5f * pw, bx2 = px + 0.5f * pw;
    float by1 = py - 0.5f * ph, by2 = py + 0.5f * ph;
    float iw = fmaxf(fminf(ax2, bx2) - fmaxf(ax1, bx1), 0.0f);
    float ih = fmaxf(fminf(ay2, by2) - fmaxf(ay1, by1), 0.0f);
    float inter = iw * ih;
    float a1 = fabsf((ax2 - ax1) * (ay2 - ay1));
    float a2 = fabsf((bx2 - bx1) * (by2 - by1));
    return inter / (a1 + a2 - inter + EPSF);
}

__global__ void __launch_bounds__(TPB, 7)
yolo_loss_kernel(const float* __restrict__ yt_g,
                 const float* __restrict__ yp_g,
                 long long n_cells,
                 long long n_wtiles,
                 float* __restrict__ out,
                 double inv_batch) {
    // [warp][stage][tensor][floats]
    __shared__ float sbuf[NWARP][2][2][WFL];   // 30720 B
    __shared__ float wsum[NWARP];
    __shared__ int   s_last;

    const int tid  = threadIdx.x;
    const int wid  = tid >> 5;
    const int lane = tid & 31;

    const long long wstride = (long long)gridDim.x * NWARP;
    long long wt = (long long)blockIdx.x * NWARP + wid;

    const uint32_t s0 =
        (uint32_t)__cvta_generic_to_shared(&sbuf[wid][0][0][0]);

    // Issue one warp-tile into stage `buf` (one commit group per call).
    auto issue = [&](long long w, int buf) {
        long long cbase = w * CW;
        uint32_t st_b = s0 + (uint32_t)(buf * 2 + 0) * (WFL * 4u);
        uint32_t sp_b = s0 + (uint32_t)(buf * 2 + 1) * (WFL * 4u);
        const float* yt = yt_g + cbase * DIM;
        const float* yp = yp_g + cbase * DIM;
        if (cbase + CW <= n_cells) {
            const float4* yt4 = (const float4*)yt;
            const float4* yp4 = (const float4*)yp;
#pragma unroll
            for (int k = 0; k < 4; k++) {
                int j = k * 32 + lane;
                if (j < NV4W) {
                    cp16(st_b + j * 16, yt4 + j);
                    cp16(sp_b + j * 16, yp4 + j);
                }
            }
        } else {
            int nflt = (int)(n_cells - cbase) * DIM;
            for (int j = lane; j < nflt; j += 32) {
                cp4(st_b + j * 4, yt + j);
                cp4(sp_b + j * 4, yp + j);
            }
        }
        asm volatile("cp.async.commit_group;\n" ::: "memory");
    };

    float acc = 0.0f;
    int buf = 0;

    if (wt < n_wtiles) issue(wt, 0);

    for (; wt < n_wtiles; wt += wstride) {
        long long nxt = wt + wstride;
        bool has_next = (nxt < n_wtiles);
        if (has_next) issue(nxt, buf ^ 1);

        if (has_next) asm volatile("cp.async.wait_group 1;\n" ::: "memory");
        else          asm volatile("cp.async.wait_group 0;\n" ::: "memory");
        __syncwarp();

        long long cbase = wt * CW;
        if (lane < CW && cbase + lane < n_cells) {
            const float* t = &sbuf[wid][buf][0][lane * DIM];
            const float* p = &sbuf[wid][buf][1][lane * DIM];

            float t0 = t[0], t1 = t[1], t2 = t[2], t3 = t[3], t4v = t[4];
            float p0 = p[0], p1 = p[1], p2 = p[2], p3 = p[3], p4 = p[4];
            float p5 = p[5], p6 = p[6], p7 = p[7], p8 = p[8], p9 = p[9];

            float obj = (t4v == 1.0f) ? 1.0f : 0.0f;

            float iou1 = iou5(t0, t1, t2, t3, p0, p1, p2, p3);
            float iou2 = iou5(t0, t1, t2, t3, p5, p6, p7, p8);
            bool best1 = iou1 > iou2;

            float bx = best1 ? p0 : p5, by = best1 ? p1 : p6;
            float bw = best1 ? p2 : p7, bh = best1 ? p3 : p8;
            float ch = best1 ? p4 : p9, oh = best1 ? p9 : p4;

            float xy = sq(t0 - bx) + sq(t1 - by);
            float wh = sq(sqrtf(t2) - sqrtf(fabsf(bw + EPSF)))
                     + sq(sqrtf(t3) - sqrtf(fabsf(bh + EPSF)));
            float obj_conf = sq(t4v - ch);
            float noio = 0.5f * oh * oh;
            float noc  = 0.5f * (sq(t4v - p4) + sq(t4v - p9));

            float cls = 0.0f;
#pragma unroll
            for (int k = 0; k < 20; k++) cls += sq(t[10 + k] - p[10 + k]);

            acc += obj * (5.0f * (xy + wh) + obj_conf + noio + cls)
                 + (1.0f - obj) * noc;
        }

        __syncwarp();   // all lanes done reading buf before it is refilled
        buf ^= 1;
    }

    // Warp reduce, then block reduce (once).
#pragma unroll
    for (int o = 16; o > 0; o >>= 1)
        acc += __shfl_xor_sync(0xFFFFFFFFu, acc, o);

    if (lane == 0) wsum[wid] = acc;
    __syncthreads();

    if (tid == 0) {
        float s = 0.0f;
#pragma unroll
        for (int i = 0; i < NWARP; i++) s += wsum[i];
        g_part[blockIdx.x] = s;
        __threadfence();
        unsigned int prev = atomicAdd(&g_count, 1u);
        s_last = (prev == gridDim.x - 1) ? 1 : 0;
    }
    __syncthreads();

    if (s_last) {
        int nb = gridDim.x;
        const volatile float* vp = g_part;
        double s = 0.0;
        for (int i = tid; i < nb; i += TPB)
            s += (double)vp[i];
#pragma unroll
        for (int o = 16; o > 0; o >>= 1)
            s += __shfl_xor_sync(0xFFFFFFFFu, s, o);

        __shared__ double dsum[NWARP];
        if (lane == 0) dsum[wid] = s;
        __syncthreads();

        if (tid == 0) {
            double tot = 0.0;
#pragma unroll
            for (int i = 0; i < NWARP; i++) tot += dsum[i];
            out[0] = (float)(tot * inv_batch);
            g_count = 0;   // reset for next graph replay
        }
    }
}

extern "C" void kernel_launch(void* const* d_in, const int* in_sizes, int n_in,
                              void* d_out, int out_size) {
    const float* yt = (const float*)d_in[0];   // y_trues
    const float* yp = (const float*)d_in[1];   // y_preds
    long long n_cells  = (long long)in_sizes[0] / DIM;    // batch * 49
    long long batch    = n_cells / 49;
    long long n_wtiles = (n_cells + CW - 1) / CW;

    // Persistent-ish grid: ~7 blocks/SM on 148-152 SMs.
    int blocks = 1064;
    long long need = (n_wtiles + NWARP - 1) / NWARP;
    if ((long long)blocks > need) blocks = (int)need;
    if (blocks > MAX_BLOCKS) blocks = MAX_BLOCKS;

    yolo_loss_kernel<<<blocks, TPB>>>(yt, yp, n_cells, n_wtiles,
                                      (float*)d_out, 1.0 / (double)batch);
}